// round 16
// baseline (speedup 1.0000x reference)
#include <cuda_runtime.h>
#include <cuda_fp16.h>
#include <cuda_bf16.h>
#include <cstddef>

#define NN 100000
#define EE 1600000
#define FULLM 0xffffffffu
#define NBLK ((NN + 255) / 256)            // 391 scan blocks
#define GEMM_BLOCKS ((NN + 63) / 64)       // 1563
#define HIST_BLOCKS ((EE / 4 + 255) / 256) // 1563

// ---------------- scratch (device globals; no allocation) ----------------
__device__ __half2 g_h1h[(size_t)NN * 32];  // packed {h[c], h[c+32]} per node
__device__ float g_asrc1[NN * 4];
__device__ float g_adst1[NN * 4];
__device__ float2 g_p2[NN];                 // {h2, asrc2}
__device__ float g_adst2[NN];
// CSR (sorted-by-dst) — REAL edges only (self-loops analytic)
__device__ int g_cnt[NN];                   // zeroed by k_scatter of the PREVIOUS run (static 0 first)
__device__ int g_start[NN + 1];
__device__ int g_pos[NN];
__device__ int g_esrc[EE];
__device__ float4 g_ee[EE];                 // per-edge exp(leaky(alpha)) per head
// decoupled-lookback scan state (flags zeroed by gemm_hist each run)
__device__ int g_part[NBLK];
__device__ int g_incl[NBLK];
__device__ int g_flag[NBLK];

// ================= K1: fused [h1 = x @ W1 + attention dots] | [dst histogram] =================
__global__ __launch_bounds__(256) void k_gemm_hist(const float* __restrict__ x,
                                                   const float* __restrict__ W1,
                                                   const float* __restrict__ att_s,
                                                   const float* __restrict__ att_d,
                                                   const int* __restrict__ ei) {
    if (blockIdx.x >= GEMM_BLOCKS) {
        int hb = blockIdx.x - GEMM_BLOCKS;
        int gid = hb * 256 + threadIdx.x;
        if (gid < NBLK) g_flag[gid] = 0;          // reset lookback flags for k_scan_lb
        if (gid < EE / 4) {
            int4 d = ((const int4*)(ei + EE))[gid];
            atomicAdd(&g_cnt[d.x], 1);
            atomicAdd(&g_cnt[d.y], 1);
            atomicAdd(&g_cnt[d.z], 1);
            atomicAdd(&g_cnt[d.w], 1);
        }
        return;
    }
    __shared__ float Wsh[64 * 64];
    __shared__ float xsh[64 * 64];
    int t = threadIdx.x;
    int n0 = blockIdx.x * 64;

    for (int i = t; i < 4096; i += 256) Wsh[i] = W1[i];
    for (int i = t; i < 4096; i += 256) {
        int n = n0 + (i >> 6);
        xsh[i] = (n < NN) ? x[(size_t)n0 * 64 + i] : 0.f;
    }
    __syncthreads();

    int tx = t & 15, ty = t >> 4;
    int lane = t & 31;
    int j0 = tx * 4;
    float acc[4][4];
#pragma unroll
    for (int i = 0; i < 4; i++)
#pragma unroll
        for (int q = 0; q < 4; q++) acc[i][q] = 0.f;

#pragma unroll 4
    for (int k4 = 0; k4 < 64; k4 += 4) {
        float4 xv[4];
#pragma unroll
        for (int i = 0; i < 4; i++)
            xv[i] = *(const float4*)&xsh[(ty * 4 + i) * 64 + k4];
#pragma unroll
        for (int kk = 0; kk < 4; kk++) {
            float4 w = *(const float4*)&Wsh[(k4 + kk) * 64 + j0];
#pragma unroll
            for (int i = 0; i < 4; i++) {
                float xvk = ((const float*)&xv[i])[kk];
                acc[i][0] = fmaf(xvk, w.x, acc[i][0]);
                acc[i][1] = fmaf(xvk, w.y, acc[i][1]);
                acc[i][2] = fmaf(xvk, w.z, acc[i][2]);
                acc[i][3] = fmaf(xvk, w.w, acc[i][3]);
            }
        }
    }

    float4 as = *(const float4*)&att_s[j0];
    float4 ad = *(const float4*)&att_d[j0];
    int head = tx >> 2;

#pragma unroll
    for (int i = 0; i < 4; i++) {
        int n = n0 + ty * 4 + i;
        float h0 = __shfl_sync(FULLM, acc[i][0], lane + 8);
        float h1v = __shfl_sync(FULLM, acc[i][1], lane + 8);
        float h2v = __shfl_sync(FULLM, acc[i][2], lane + 8);
        float h3v = __shfl_sync(FULLM, acc[i][3], lane + 8);
        if (tx < 8 && n < NN) {
            __half2 p0 = __floats2half2_rn(acc[i][0], h0);
            __half2 p1 = __floats2half2_rn(acc[i][1], h1v);
            __half2 p2 = __floats2half2_rn(acc[i][2], h2v);
            __half2 p3 = __floats2half2_rn(acc[i][3], h3v);
            uint4 u = make_uint4(*(unsigned*)&p0, *(unsigned*)&p1,
                                 *(unsigned*)&p2, *(unsigned*)&p3);
            *(uint4*)&g_h1h[(size_t)n * 32 + j0] = u;
        }
        float ps = acc[i][0] * as.x + acc[i][1] * as.y + acc[i][2] * as.z + acc[i][3] * as.w;
        float pd = acc[i][0] * ad.x + acc[i][1] * ad.y + acc[i][2] * ad.z + acc[i][3] * ad.w;
        ps += __shfl_xor_sync(FULLM, ps, 1);
        ps += __shfl_xor_sync(FULLM, ps, 2);
        pd += __shfl_xor_sync(FULLM, pd, 1);
        pd += __shfl_xor_sync(FULLM, pd, 2);
        if ((tx & 3) == 0 && n < NN) {
            g_asrc1[n * 4 + head] = ps;
            g_adst1[n * 4 + head] = pd;
        }
    }
}

// ================= K2: single-pass scan with warp-parallel decoupled lookback =================
__global__ __launch_bounds__(256) void k_scan_lb() {
    int b = blockIdx.x;
    int idx = b * 256 + threadIdx.x;
    int lane = threadIdx.x & 31;
    int w = threadIdx.x >> 5;
    int c = (idx < NN) ? g_cnt[idx] : 0;

    int v = c;
#pragma unroll
    for (int off = 1; off < 32; off <<= 1) {
        int u = __shfl_up_sync(FULLM, v, off);
        if (lane >= off) v += u;
    }
    __shared__ int wtot[8];
    __shared__ int s_btot;
    __shared__ int s_off;
    if (lane == 31) wtot[w] = v;
    __syncthreads();
    if (threadIdx.x < 8) {
        int a = wtot[threadIdx.x];
        int p = a;
#pragma unroll
        for (int off = 1; off < 8; off <<= 1) {
            int u = __shfl_up_sync(0xffu, p, off);
            if (threadIdx.x >= off) p += u;
        }
        if (threadIdx.x == 7) s_btot = p;
        wtot[threadIdx.x] = p - a;
    }
    __syncthreads();
    int btot = s_btot;

    if (w == 0) {
        if (lane == 0 && b > 0) {
            g_part[b] = btot;
            __threadfence();
            atomicExch(&g_flag[b], 1);
        }
        int offset = 0;
        if (b > 0) {
            int i = b - 1;
            volatile int* vf = g_flag;
            volatile int* vp = g_part;
            volatile int* vi = g_incl;
            for (;;) {
                int id = i - lane;
                int f = 2, val = 0;
                if (id >= 0) {
                    f = vf[id];
                    val = (f == 2) ? vi[id] : ((f == 1) ? vp[id] : 0);
                }
                unsigned notready = __ballot_sync(FULLM, id >= 0 && f == 0);
                if (notready) continue;
                unsigned inclmask = __ballot_sync(FULLM, id < 0 || f == 2);
                int stop = inclmask ? (__ffs(inclmask) - 1) : 32;
                int contrib = ((lane < stop) || (lane == stop && id >= 0)) ? val : 0;
#pragma unroll
                for (int off = 16; off; off >>= 1) contrib += __shfl_xor_sync(FULLM, contrib, off);
                offset += contrib;
                if (stop < 32) break;
                i -= 32;
            }
        }
        if (lane == 0) {
            g_incl[b] = offset + btot;
            __threadfence();
            atomicExch(&g_flag[b], 2);
            s_off = offset;
        }
    }
    __syncthreads();
    int excl = s_off + wtot[w] + (v - c);
    if (idx < NN) { g_start[idx] = excl; g_pos[idx] = excl; }
    if (idx == 0) g_start[NN] = EE;
}

// ================= K3: scatter src + per-edge exp vector; re-zero g_cnt for next run =================
__global__ __launch_bounds__(256) void k_scatter(const int* __restrict__ ei) {
    int t = blockIdx.x * 256 + threadIdx.x;
    if (t >= EE / 4) return;
    if (t < NN) g_cnt[t] = 0;
    int4 s4 = ((const int4*)ei)[t];
    int4 d4 = ((const int4*)(ei + EE))[t];
    int ss[4] = {s4.x, s4.y, s4.z, s4.w};
    int dd[4] = {d4.x, d4.y, d4.z, d4.w};
    int pp[4];
#pragma unroll
    for (int k = 0; k < 4; k++) pp[k] = atomicAdd(&g_pos[dd[k]], 1);
#pragma unroll
    for (int k = 0; k < 4; k++) {
        float4 as = *(const float4*)&g_asrc1[ss[k] * 4];
        float4 ad = *(const float4*)&g_adst1[dd[k] * 4];
        float a0 = as.x + ad.x; a0 = a0 > 0.f ? a0 : 0.2f * a0;
        float a1 = as.y + ad.y; a1 = a1 > 0.f ? a1 : 0.2f * a1;
        float a2 = as.z + ad.z; a2 = a2 > 0.f ? a2 : 0.2f * a2;
        float a3 = as.w + ad.w; a3 = a3 > 0.f ? a3 : 0.2f * a3;
        float4 e = make_float4(__expf(a0), __expf(a1), __expf(a2), __expf(a3));
        g_esrc[pp[k]] = ss[k];
        g_ee[pp[k]] = e;
    }
}

// ================= K4: layer-1 gather: half-warp per edge, 4ch/lane =================
// Lane L=lane&15, hw=lane>>4. Lane channels: c0=2L, c1=2L+1, c2=2L+32, c3=2L+33.
// Head of (c0,c1): L<8 ? 0 : 1; head of (c2,c3): L<8 ? 2 : 3.
__global__ __launch_bounds__(256) void k_gather1(const float* __restrict__ b1,
                                                 const float* __restrict__ W2,
                                                 const float* __restrict__ as2,
                                                 const float* __restrict__ ad2) {
    __shared__ int    s_src[8][32];
    __shared__ float2 s_ee[8][2][32];    // [warp][headPairSel][slot] = {eLow, eHigh}
    int wIn = threadIdx.x >> 5;
    int lane = threadIdx.x & 31;
    int L = lane & 15;
    int hw = lane >> 4;
    int n = blockIdx.x * 8 + wIn;
    if (n >= NN) return;

    int s = g_start[n], eend = g_start[n + 1];

    float acc0 = 0.f, acc1 = 0.f, acc2 = 0.f, acc3 = 0.f;
    float d0 = 0.f, d1 = 0.f, d2 = 0.f, d3 = 0.f;

    const float2* ep = s_ee[wIn][L >> 3];   // L<8 -> {e0,e2}, else {e1,e3}

    for (int base = s; base < eend; base += 32) {
        int j = base + lane;
        bool v = (j < eend);
        int sj = v ? g_esrc[j] : 0;
        float4 ev = v ? g_ee[j] : make_float4(0.f, 0.f, 0.f, 0.f);
        d0 += ev.x; d1 += ev.y; d2 += ev.z; d3 += ev.w;
        s_src[wIn][lane] = sj;
        s_ee[wIn][0][lane] = make_float2(ev.x, ev.z);
        s_ee[wIn][1][lane] = make_float2(ev.y, ev.w);
        __syncwarp();

        int cnt = eend - base; if (cnt > 32) cnt = 32;
        int q = 0;
        // 4 pairs (8 edges) per unrolled step; each half-warp owns one edge per pair
        for (; q + 8 <= cnt; q += 8) {
            uint2 hv[4];
            float2 eq[4];
#pragma unroll
            for (int u = 0; u < 4; u++) {
                int slot = q + u * 2 + hw;
                int sq = s_src[wIn][slot];
                hv[u] = *(const uint2*)&g_h1h[(size_t)sq * 32 + 2 * L];
                eq[u] = ep[slot];
            }
#pragma unroll
            for (int u = 0; u < 4; u++) {
                float2 fa = __half22float2(*(__half2*)&hv[u].x);  // {c0, c2}
                float2 fb = __half22float2(*(__half2*)&hv[u].y);  // {c1, c3}
                acc0 = fmaf(fa.x, eq[u].x, acc0);
                acc2 = fmaf(fa.y, eq[u].y, acc2);
                acc1 = fmaf(fb.x, eq[u].x, acc1);
                acc3 = fmaf(fb.y, eq[u].y, acc3);
            }
        }
        for (; q + 2 <= cnt; q += 2) {
            int slot = q + hw;
            int sq = s_src[wIn][slot];
            uint2 hv = *(const uint2*)&g_h1h[(size_t)sq * 32 + 2 * L];
            float2 eq = ep[slot];
            float2 fa = __half22float2(*(__half2*)&hv.x);
            float2 fb = __half22float2(*(__half2*)&hv.y);
            acc0 = fmaf(fa.x, eq.x, acc0);
            acc2 = fmaf(fa.y, eq.y, acc2);
            acc1 = fmaf(fb.x, eq.x, acc1);
            acc3 = fmaf(fb.y, eq.y, acc3);
        }
        if (q < cnt && hw == 0) {   // odd tail: half-warp 0 only
            int sq = s_src[wIn][q];
            uint2 hv = *(const uint2*)&g_h1h[(size_t)sq * 32 + 2 * L];
            float2 eq = ep[q];
            float2 fa = __half22float2(*(__half2*)&hv.x);
            float2 fb = __half22float2(*(__half2*)&hv.y);
            acc0 = fmaf(fa.x, eq.x, acc0);
            acc2 = fmaf(fa.y, eq.y, acc2);
            acc1 = fmaf(fb.x, eq.x, acc1);
            acc3 = fmaf(fb.y, eq.y, acc3);
        }
        __syncwarp();
    }

    // merge halves (lanes L and L+16 hold same channels)
    acc0 += __shfl_xor_sync(FULLM, acc0, 16);
    acc1 += __shfl_xor_sync(FULLM, acc1, 16);
    acc2 += __shfl_xor_sync(FULLM, acc2, 16);
    acc3 += __shfl_xor_sync(FULLM, acc3, 16);

    // denominators (full-warp reduce)
#pragma unroll
    for (int off = 16; off; off >>= 1) {
        d0 += __shfl_xor_sync(FULLM, d0, off);
        d1 += __shfl_xor_sync(FULLM, d1, off);
        d2 += __shfl_xor_sync(FULLM, d2, off);
        d3 += __shfl_xor_sync(FULLM, d3, off);
    }

    // self-loop (analytic; all lanes compute redundantly)
    float4 asn = *(const float4*)&g_asrc1[n * 4];
    float4 adn = *(const float4*)&g_adst1[n * 4];
    float sa0 = asn.x + adn.x; sa0 = sa0 > 0.f ? sa0 : 0.2f * sa0;
    float sa1 = asn.y + adn.y; sa1 = sa1 > 0.f ? sa1 : 0.2f * sa1;
    float sa2 = asn.z + adn.z; sa2 = sa2 > 0.f ? sa2 : 0.2f * sa2;
    float sa3 = asn.w + adn.w; sa3 = sa3 > 0.f ? sa3 : 0.2f * sa3;
    float se0 = __expf(sa0), se1 = __expf(sa1), se2 = __expf(sa2), se3 = __expf(sa3);
    float seA = (L < 8) ? se0 : se1;
    float seB = (L < 8) ? se2 : se3;

    uint2 hvs = *(const uint2*)&g_h1h[(size_t)n * 32 + 2 * L];
    float2 sfa = __half22float2(*(__half2*)&hvs.x);   // {c0, c2}
    float2 sfb = __half22float2(*(__half2*)&hvs.y);   // {c1, c3}
    acc0 = fmaf(sfa.x, seA, acc0);
    acc2 = fmaf(sfa.y, seB, acc2);
    acc1 = fmaf(sfb.x, seA, acc1);
    acc3 = fmaf(sfb.y, seB, acc3);

    float dA = ((L < 8) ? d0 : d1) + seA;
    float dB = ((L < 8) ? d2 : d3) + seB;

    float2 b01 = *(const float2*)&b1[2 * L];
    float2 b23 = *(const float2*)&b1[2 * L + 32];
    float rA = 1.f / (dA + 1e-16f);
    float rB = 1.f / (dB + 1e-16f);
    float o0 = acc0 * rA + b01.x;
    float o1 = acc1 * rA + b01.y;
    float o2 = acc2 * rB + b23.x;
    float o3 = acc3 * rB + b23.y;
    o0 = o0 > 0.f ? o0 : expm1f(o0);
    o1 = o1 > 0.f ? o1 : expm1f(o1);
    o2 = o2 > 0.f ? o2 : expm1f(o2);
    o3 = o3 > 0.f ? o3 : expm1f(o3);

    float2 w01 = *(const float2*)&W2[2 * L];
    float2 w23 = *(const float2*)&W2[2 * L + 32];
    float p = o0 * w01.x + o1 * w01.y + o2 * w23.x + o3 * w23.y;
    // reduce over 16 lanes (halves are identical)
    p += __shfl_xor_sync(FULLM, p, 8);
    p += __shfl_xor_sync(FULLM, p, 4);
    p += __shfl_xor_sync(FULLM, p, 2);
    p += __shfl_xor_sync(FULLM, p, 1);

    if (lane == 0) {
        g_p2[n] = make_float2(p, p * as2[0]);   // {h2, asrc2}
        g_adst2[n] = p * ad2[0];
    }
}

// ================= K5: layer-2 gather + output; 2 nodes per warp =================
__global__ __launch_bounds__(256) void k_gather2(float* __restrict__ out,
                                                 const float* __restrict__ b2) {
    int gw = (blockIdx.x * 256 + threadIdx.x) >> 5;
    int lane = threadIdx.x & 31;
    int L = lane & 15;
    int hw = lane >> 4;
    int n = gw * 2 + hw;            // NN even: always < NN for gw < NN/2
    if (n >= NN) return;

    int s = g_start[n], eend = g_start[n + 1];
    float adn = g_adst2[n];
    float2 pn = g_p2[n];
    float num = 0.f, den = 0.f;
    for (int j = s + L; j < eend; j += 16) {
        int src = g_esrc[j];
        float2 hs = g_p2[src];
        float a = hs.y + adn;
        a = a > 0.f ? a : 0.2f * a;
        float e = __expf(a);
        den += e;
        num = fmaf(hs.x, e, num);
    }
    // reduce within half-warp
    num += __shfl_xor_sync(FULLM, num, 8);
    den += __shfl_xor_sync(FULLM, den, 8);
    num += __shfl_xor_sync(FULLM, num, 4);
    den += __shfl_xor_sync(FULLM, den, 4);
    num += __shfl_xor_sync(FULLM, num, 2);
    den += __shfl_xor_sync(FULLM, den, 2);
    num += __shfl_xor_sync(FULLM, num, 1);
    den += __shfl_xor_sync(FULLM, den, 1);

    if (L == 0) {
        float a = pn.y + adn;
        a = a > 0.f ? a : 0.2f * a;
        float e = __expf(a);
        den += e;
        num = fmaf(pn.x, e, num);
        out[n] = num / (den + 1e-16f) + b2[0];
    }
}

// ---------------- launch ----------------
extern "C" void kernel_launch(void* const* d_in, const int* in_sizes, int n_in,
                              void* d_out, int out_size) {
    const float* x   = (const float*)d_in[0];
    const int*   ei  = (const int*)d_in[1];
    const float* W1  = (const float*)d_in[2];
    const float* as1 = (const float*)d_in[3];
    const float* ad1 = (const float*)d_in[4];
    const float* b1  = (const float*)d_in[5];
    const float* W2  = (const float*)d_in[6];
    const float* as2 = (const float*)d_in[7];
    const float* ad2 = (const float*)d_in[8];
    const float* b2  = (const float*)d_in[9];
    float* out = (float*)d_out;

    k_gemm_hist<<<GEMM_BLOCKS + HIST_BLOCKS, 256>>>(x, W1, as1, ad1, ei);
    k_scan_lb  <<<NBLK, 256>>>();
    k_scatter  <<<(EE / 4 + 255) / 256, 256>>>(ei);
    k_gather1  <<<(NN + 7) / 8, 256>>>(b1, W2, as2, ad2);
    k_gather2  <<<(NN / 2 * 32 + 255) / 256, 256>>>(out, b2);
}